// round 3
// baseline (speedup 1.0000x reference)
#include <cuda_runtime.h>
#include <cuda_bf16.h>

#define FULL_MASK 0xffffffffu

static constexpr int Bb = 256;
static constexpr int Tt = 2048;
static constexpr float INV_LN2 = 1.4426950408889634f;
static constexpr float LN2     = 0.6931471805599453f;

__device__ __forceinline__ float ex2f(float x) {
    float r; asm("ex2.approx.f32 %0, %1;" : "=f"(r) : "f"(x)); return r;
}
__device__ __forceinline__ float lg2f(float x) {
    float r; asm("lg2.approx.f32 %0, %1;" : "=f"(r) : "f"(x)); return r;
}
// packs {hi, lo} -> bf16x2
__device__ __forceinline__ unsigned cvt_bf16x2(float hi, float lo) {
    unsigned r; asm("cvt.rn.bf16x2.f32 %0, %1, %2;" : "=r"(r) : "f"(hi), "f"(lo)); return r;
}
__device__ __forceinline__ unsigned hfma2b(unsigned a, unsigned b, unsigned c) {
    unsigned r; asm("fma.rn.bf16x2 %0, %1, %2, %3;" : "=r"(r) : "r"(a), "r"(b), "r"(c)); return r;
}
__device__ __forceinline__ float bf_lo(unsigned v) { return __uint_as_float(v << 16); }
__device__ __forceinline__ float bf_hi(unsigned v) { return __uint_as_float(v & 0xFFFF0000u); }

struct Chain {
    const float2* pb;   // p base (+lane offset), float2 per lane
    const int2*   yb;
    float ax, ay;       // alpha (log2 domain) for d0, d1
    float del1, del2;   // stale normalizers (t-2, t-1)
    float s1, s2;       // emission / transition partials
    float pend1, pend2; // pipelined transition gathers
    int   prevE;        // my previous-step label if I own it, else -1
    int   L;
    float2 pf[4];
    int2   yf[4];
};

__device__ __forceinline__ int seq_len(const int* mask, int b, int l) {
    int cnt = 0;
    const int* mb = mask + (size_t)b * Tt;
    #pragma unroll 8
    for (int t = l; t < Tt; t += 32) cnt += (mb[t] == 0);
    #pragma unroll
    for (int o = 16; o; o >>= 1) cnt += __shfl_xor_sync(FULL_MASK, cnt, o);
    return cnt;
}

__device__ __forceinline__ void chain_init(Chain& C, const float* p, const int* y,
                                           const int* mask, int b, int l, int d0) {
    C.L  = seq_len(mask, b, l);
    C.pb = reinterpret_cast<const float2*>(p) + (size_t)b * Tt * 32 + l;
    C.yb = reinterpret_cast<const int2*>(y)  + (size_t)b * Tt * 32 + l;
    float2 p0 = C.pb[0];
    int2   y0 = C.yb[0];
    C.ax = p0.x * INV_LN2;
    C.ay = p0.y * INV_LN2;
    C.s1 = 0.f;
    if (y0.x) C.s1 += p0.x;
    if (y0.y) C.s1 += p0.y;
    C.prevE = y0.x ? d0 : (y0.y ? (d0 + 1) : -1);
    C.del1 = C.del2 = __shfl_sync(FULL_MASK, C.ax, 0);
    C.s2 = 0.f; C.pend1 = 0.f; C.pend2 = 0.f;
    #pragma unroll
    for (int i = 0; i < 4; ++i) {
        C.pf[i] = C.pb[(size_t)(1 + i) * 32];
        C.yf[i] = C.yb[(size_t)(1 + i) * 32];
    }
}

// phase 1: prefetch rotate + write normalized exp(alpha) to shared (dup bf16x2)
__device__ __forceinline__ void step_write(Chain& C, int t, int i, int l, unsigned* buf) {
    int tn = t + 4; if (tn > Tt - 1) tn = Tt - 1;
    float2 pt = C.pf[i];  int2 yv = C.yf[i];
    C.pf[i] = C.pb[(size_t)tn * 32];
    C.yf[i] = C.yb[(size_t)tn * 32];
    float A0 = ex2f(C.ax - C.del1);
    float A1 = ex2f(C.ay - C.del1);
    reinterpret_cast<uint2*>(buf)[l] =
        make_uint2(cvt_bf16x2(A0, A0), cvt_bf16x2(A1, A1));
    // stash current pt/yv back into pf/yf slot? no — pass via registers:
    C.pf[3] = C.pf[3]; // (no-op; pt/yv handled by caller)
    (void)pt; (void)yv;
}

__global__ __launch_bounds__(32, 16) void crf_forward_kernel(
    const float* __restrict__ p,
    const int*   __restrict__ y,
    const int*   __restrict__ mask,
    const float* __restrict__ tr,
    float*       __restrict__ out)
{
    const int l  = threadIdx.x;
    const int d0 = 2 * l;
    const int b0 = blockIdx.x;
    const int b1 = blockIdx.x + Bb / 2;

    __shared__ unsigned shA[2][2][64];  // [chain][parity][e]

    // shared exp(transition) columns, bf16x2 {lo=expT[e][d0], hi=expT[e][d1]}
    unsigned mtpb[64];
    {
        const float2* trp = reinterpret_cast<const float2*>(tr);
        #pragma unroll
        for (int e = 0; e < 64; ++e) {
            float2 v = trp[e * 32 + l];
            mtpb[e] = cvt_bf16x2(__expf(v.y), __expf(v.x));
        }
    }

    Chain C0, C1;
    chain_init(C0, p, y, mask, b0, l, d0);
    chain_init(C1, p, y, mask, b1, l, d0);
    const int Lmax = (C0.L > C1.L) ? C0.L : C1.L;

    for (int tb = 1; tb < Lmax; tb += 4) {
        #pragma unroll
        for (int i = 0; i < 4; ++i) {
            const int t = tb + i;
            const int q = t & 1;

            // ---- consume prefetched, rotate prefetch (distance 4)
            int tn = t + 4; if (tn > Tt - 1) tn = Tt - 1;
            float2 pt0 = C0.pf[i]; int2 yv0 = C0.yf[i];
            float2 pt1 = C1.pf[i]; int2 yv1 = C1.yf[i];
            C0.pf[i] = C0.pb[(size_t)tn * 32]; C0.yf[i] = C0.yb[(size_t)tn * 32];
            C1.pf[i] = C1.pb[(size_t)tn * 32]; C1.yf[i] = C1.yb[(size_t)tn * 32];

            // ---- write A (both chains), one sync
            float A00 = ex2f(C0.ax - C0.del1);
            float A01 = ex2f(C0.ay - C0.del1);
            float A10 = ex2f(C1.ax - C1.del1);
            float A11 = ex2f(C1.ay - C1.del1);
            reinterpret_cast<uint2*>(shA[0][q])[l] =
                make_uint2(cvt_bf16x2(A00, A00), cvt_bf16x2(A01, A01));
            reinterpret_cast<uint2*>(shA[1][q])[l] =
                make_uint2(cvt_bf16x2(A10, A10), cvt_bf16x2(A11, A11));
            __syncwarp();

            // ---- dual inner products (compiler interleaves the two chains)
            const uint4* s40 = reinterpret_cast<const uint4*>(shA[0][q]);
            const uint4* s41 = reinterpret_cast<const uint4*>(shA[1][q]);
            unsigned a0 = 0, a1 = 0, a2 = 0, a3 = 0;
            unsigned c0 = 0, c1 = 0, c2 = 0, c3 = 0;
            #pragma unroll
            for (int g = 0; g < 16; ++g) {
                uint4 v0 = s40[g];
                uint4 v1 = s41[g];
                a0 = hfma2b(v0.x, mtpb[4 * g + 0], a0);
                c0 = hfma2b(v1.x, mtpb[4 * g + 0], c0);
                a1 = hfma2b(v0.y, mtpb[4 * g + 1], a1);
                c1 = hfma2b(v1.y, mtpb[4 * g + 1], c1);
                a2 = hfma2b(v0.z, mtpb[4 * g + 2], a2);
                c2 = hfma2b(v1.z, mtpb[4 * g + 2], c2);
                a3 = hfma2b(v0.w, mtpb[4 * g + 3], a3);
                c3 = hfma2b(v1.w, mtpb[4 * g + 3], c3);
            }
            float sx0 = (bf_lo(a0) + bf_lo(a1)) + (bf_lo(a2) + bf_lo(a3));
            float sy0 = (bf_hi(a0) + bf_hi(a1)) + (bf_hi(a2) + bf_hi(a3));
            float sx1 = (bf_lo(c0) + bf_lo(c1)) + (bf_lo(c2) + bf_lo(c3));
            float sy1 = (bf_hi(c0) + bf_hi(c1)) + (bf_hi(c2) + bf_hi(c3));

            const bool v0ok = t < C0.L;
            const bool v1ok = t < C1.L;

            // ---- alpha update (log2 domain), predicated freeze
            float ax0n = fmaf(pt0.x, INV_LN2, C0.del1 + lg2f(sx0));
            float ay0n = fmaf(pt0.y, INV_LN2, C0.del1 + lg2f(sy0));
            float ax1n = fmaf(pt1.x, INV_LN2, C1.del1 + lg2f(sx1));
            float ay1n = fmaf(pt1.y, INV_LN2, C1.del1 + lg2f(sy1));
            C0.ax = v0ok ? ax0n : C0.ax;  C0.ay = v0ok ? ay0n : C0.ay;
            C1.ax = v1ok ? ax1n : C1.ax;  C1.ay = v1ok ? ay1n : C1.ay;
            C0.del1 = C0.del2;  C0.del2 = __shfl_sync(FULL_MASK, C0.ax, 0);
            C1.del1 = C1.del2;  C1.del2 = __shfl_sync(FULL_MASK, C1.ax, 0);

            // ---- scores (off critical path)
            if (v0ok && yv0.x) C0.s1 += pt0.x;
            if (v0ok && yv0.y) C0.s1 += pt0.y;
            if (v1ok && yv1.x) C1.s1 += pt1.x;
            if (v1ok && yv1.y) C1.s1 += pt1.y;

            unsigned bal0  = __ballot_sync(FULL_MASK, (yv0.x | yv0.y) != 0);
            unsigned baly0 = __ballot_sync(FULL_MASK, yv0.y != 0);
            unsigned bal1  = __ballot_sync(FULL_MASK, (yv1.x | yv1.y) != 0);
            unsigned baly1 = __ballot_sync(FULL_MASK, yv1.y != 0);
            int src0 = __ffs(bal0) - 1;
            int lab0 = 2 * src0 + ((baly0 >> src0) & 1);
            int src1 = __ffs(bal1) - 1;
            int lab1 = 2 * src1 + ((baly1 >> src1) & 1);

            float g0 = (v0ok && C0.prevE >= 0) ? __ldg(&tr[C0.prevE * 64 + lab0]) : 0.f;
            float g1 = (v1ok && C1.prevE >= 0) ? __ldg(&tr[C1.prevE * 64 + lab1]) : 0.f;
            C0.s2 += C0.pend1; C0.pend1 = C0.pend2; C0.pend2 = g0;
            C1.s2 += C1.pend1; C1.pend1 = C1.pend2; C1.pend2 = g1;
            C0.prevE = yv0.x ? d0 : (yv0.y ? (d0 + 1) : -1);
            C1.prevE = yv1.x ? d0 : (yv1.y ? (d0 + 1) : -1);
        }
    }
    C0.s2 += C0.pend1 + C0.pend2;
    C1.s2 += C1.pend1 + C1.pend2;

    // ---- finalize both chains
    #pragma unroll
    for (int c = 0; c < 2; ++c) {
        Chain& C = c ? C1 : C0;
        float m = fmaxf(C.ax, C.ay);
        #pragma unroll
        for (int o = 16; o; o >>= 1) m = fmaxf(m, __shfl_xor_sync(FULL_MASK, m, o));
        float se = ex2f(C.ax - m) + ex2f(C.ay - m);
        float s1 = C.s1, s2 = C.s2;
        #pragma unroll
        for (int o = 16; o; o >>= 1) {
            se += __shfl_xor_sync(FULL_MASK, se, o);
            s1 += __shfl_xor_sync(FULL_MASK, s1, o);
            s2 += __shfl_xor_sync(FULL_MASK, s2, o);
        }
        if (l == 0) out[c ? b1 : b0] = LN2 * (m + lg2f(se)) - s1 - s2;
    }
}

extern "C" void kernel_launch(void* const* d_in, const int* in_sizes, int n_in,
                              void* d_out, int out_size) {
    const float* p    = (const float*)d_in[0];
    const int*   y    = (const int*)d_in[1];
    const int*   mask = (const int*)d_in[2];
    const float* tr   = (const float*)d_in[3];
    float* out = (float*)d_out;

    crf_forward_kernel<<<Bb / 2, 32>>>(p, y, mask, tr, out);
}

// round 5
// speedup vs baseline: 1.5037x; 1.5037x over previous
#include <cuda_runtime.h>
#include <cuda_bf16.h>

#define FULL_MASK 0xffffffffu

static constexpr int Bb = 256;
static constexpr int Tt = 2048;
static constexpr float INV_LN2 = 1.4426950408889634f;
static constexpr float LN2     = 0.6931471805599453f;

__device__ float g_s12[Bb];   // s1+s2 per batch, written by score kernel

__device__ __forceinline__ float ex2f(float x) {
    float r; asm("ex2.approx.f32 %0, %1;" : "=f"(r) : "f"(x)); return r;
}
__device__ __forceinline__ float lg2f(float x) {
    float r; asm("lg2.approx.f32 %0, %1;" : "=f"(r) : "f"(x)); return r;
}
// packs (hi, lo) -> bf16x2
__device__ __forceinline__ unsigned cvt_bf16x2(float hi, float lo) {
    unsigned r; asm("cvt.rn.bf16x2.f32 %0, %1, %2;" : "=r"(r) : "f"(hi), "f"(lo)); return r;
}
__device__ __forceinline__ unsigned hfma2b(unsigned a, unsigned b, unsigned c) {
    unsigned r; asm("fma.rn.bf16x2 %0, %1, %2, %3;" : "=r"(r) : "r"(a), "r"(b), "r"(c)); return r;
}
__device__ __forceinline__ float bf_lo(unsigned v) { return __uint_as_float(v << 16); }
__device__ __forceinline__ float bf_hi(unsigned v) { return __uint_as_float(v & 0xFFFF0000u); }

// ============================================================================
// Kernel 1: scores (s1 emission + s2 transition), fully parallel over (b,t)
// ============================================================================
__global__ __launch_bounds__(512) void crf_scores(
    const float* __restrict__ p,
    const int*   __restrict__ y,
    const int*   __restrict__ mask,
    const float* __restrict__ tr)
{
    const int b   = blockIdx.x;
    const int tid = threadIdx.x;
    const int l   = tid & 31;
    const int w   = tid >> 5;          // 16 warps

    __shared__ short labs[Tt];
    __shared__ int   sL;
    __shared__ float red[16];

    if (tid == 0) sL = 0;
    __syncthreads();

    // sequence length
    int cnt = 0;
    const int* mb = mask + (size_t)b * Tt;
    for (int t = tid; t < Tt; t += 512) cnt += (mb[t] == 0);
    #pragma unroll
    for (int o = 16; o; o >>= 1) cnt += __shfl_xor_sync(FULL_MASK, cnt, o);
    if (l == 0) atomicAdd(&sL, cnt);
    __syncthreads();
    const int L = sL;

    // labels via ballot; warp w handles t in [w*128, w*128+128)
    const int2* yb = reinterpret_cast<const int2*>(y) + (size_t)b * Tt * 32 + l;
    float s1 = 0.f;
    for (int k = 0; k < 128; ++k) {
        int t = w * 128 + k;
        int2 yv = yb[(size_t)t * 32];
        unsigned balx = __ballot_sync(FULL_MASK, yv.x != 0);
        unsigned baly = __ballot_sync(FULL_MASK, yv.y != 0);
        int srcl = __ffs(balx | baly) - 1;
        int lab  = 2 * srcl + ((baly >> srcl) & 1);
        if (l == 0) labs[t] = (short)lab;
        if (l == srcl && t < L)
            s1 += __ldg(&p[((size_t)(b * Tt + t) << 6) + lab]);
    }
    __syncthreads();

    // transition score over valid bigrams: t in [0, L-1)
    float s2 = 0.f;
    for (int t = tid; t < L - 1; t += 512)
        s2 += __ldg(&tr[(int)labs[t] * 64 + (int)labs[t + 1]]);

    // block reduce s1+s2
    float s = s1 + s2;
    #pragma unroll
    for (int o = 16; o; o >>= 1) s += __shfl_xor_sync(FULL_MASK, s, o);
    if (l == 0) red[w] = s;
    __syncthreads();
    if (tid == 0) {
        float tot = 0.f;
        #pragma unroll
        for (int i = 0; i < 16; ++i) tot += red[i];
        g_s12[b] = tot;
    }
}

// ============================================================================
// Kernel 2: forward recursion in pure exp domain (no log/exp on the chain).
// 2 warps/block (separate SMSPs), one batch element per warp.
// Lane l owns d0=2l, d1=2l+1.
// ============================================================================
__global__ __launch_bounds__(64, 1) void crf_forward(
    const float* __restrict__ p,
    const int*   __restrict__ mask,
    const float* __restrict__ tr,
    float*       __restrict__ out)
{
    const int wid = threadIdx.x >> 5;
    const int l   = threadIdx.x & 31;
    const int b   = blockIdx.x * 2 + wid;

    __shared__ unsigned shA[2][2][64];  // [warp][parity][e], dup bf16x2 {A,A}

    // E = exp(transition), columns (d0,d1) packed bf16x2 {lo=d0, hi=d1}
    unsigned Eb[64];
    const float2* trp = reinterpret_cast<const float2*>(tr);
    #pragma unroll
    for (int e = 0; e < 64; ++e) {
        float2 v = trp[e * 32 + l];
        Eb[e] = cvt_bf16x2(__expf(v.y), __expf(v.x));
    }

    // sequence length
    int cnt = 0;
    const int* mb = mask + (size_t)b * Tt;
    #pragma unroll 8
    for (int t = l; t < Tt; t += 32) cnt += (mb[t] == 0);
    #pragma unroll
    for (int o = 16; o; o >>= 1) cnt += __shfl_xor_sync(FULL_MASK, cnt, o);
    const int L = cnt;  // >= T/2

    const float2* pb = reinterpret_cast<const float2*>(p) + (size_t)b * Tt * 32 + l;

    // ---- init: A_0 = exp2(p0/ln2 - c0), c0 = p0[0]/ln2 (uniform)
    float2 p0 = pb[0];
    float c0 = __shfl_sync(FULL_MASK, p0.x, 0) * INV_LN2;
    float vx = ex2f(fmaf(p0.x, INV_LN2, -c0));
    float vy = ex2f(fmaf(p0.y, INV_LN2, -c0));
    reinterpret_cast<uint2*>(shA[wid][0])[l] =
        make_uint2(cvt_bf16x2(vx, vx), cvt_bf16x2(vy, vy));
    float logC = c0;
    __syncwarp();
    // normalizer for next step, from shared (broadcast LDS, no shuffle)
    float cq = lg2f(__uint_as_float(shA[wid][0][0] << 16));

    // prefetch p, distance 6
    float2 pf[6];
    #pragma unroll
    for (int i = 0; i < 6; ++i) pf[i] = pb[(size_t)(1 + i) * 32];

    for (int tb = 1; tb < Tt; tb += 6) {
        #pragma unroll
        for (int i = 0; i < 6; ++i) {
            const int t = tb + i;
            if (t >= L) break;                     // warp-uniform

            float2 pt = pf[i];
            int tn = t + 6; if (tn > Tt - 1) tn = Tt - 1;
            pf[i] = pb[(size_t)tn * 32];

            // em = exp(p_t) * 2^{-cq}   (off the critical chain)
            float emx = ex2f(fmaf(pt.x, INV_LN2, -cq));
            float emy = ex2f(fmaf(pt.y, INV_LN2, -cq));
            logC += cq;

            // dot: s[d] = sum_e A[e] * E[e][d], bf16x2 packed
            const uint4* sa = reinterpret_cast<const uint4*>(shA[wid][(t - 1) & 1]);
            unsigned a0 = 0, a1 = 0, a2 = 0, a3 = 0;
            #pragma unroll
            for (int g = 0; g < 16; ++g) {
                uint4 v = sa[g];
                a0 = hfma2b(v.x, Eb[4 * g + 0], a0);
                a1 = hfma2b(v.y, Eb[4 * g + 1], a1);
                a2 = hfma2b(v.z, Eb[4 * g + 2], a2);
                a3 = hfma2b(v.w, Eb[4 * g + 3], a3);
            }
            float sx = (bf_lo(a0) + bf_lo(a1)) + (bf_lo(a2) + bf_lo(a3));
            float sy = (bf_hi(a0) + bf_hi(a1)) + (bf_hi(a2) + bf_hi(a3));

            vx = sx * emx;
            vy = sy * emy;
            reinterpret_cast<uint2*>(shA[wid][t & 1])[l] =
                make_uint2(cvt_bf16x2(vx, vx), cvt_bf16x2(vy, vy));
            __syncwarp();

            // next normalizer from just-written A_t[0] (safe until t+2 overwrite)
            cq = lg2f(__uint_as_float(shA[wid][t & 1][0] << 16));
        }
        if (tb + 6 >= L) break;
    }

    // ---- logZ = LN2 * (log2(sum_d A_{L-1}) + logC)
    float s = vx + vy;
    #pragma unroll
    for (int o = 16; o; o >>= 1) s += __shfl_xor_sync(FULL_MASK, s, o);
    if (l == 0) out[b] = LN2 * (lg2f(s) + logC) - g_s12[b];
}

extern "C" void kernel_launch(void* const* d_in, const int* in_sizes, int n_in,
                              void* d_out, int out_size) {
    const float* p    = (const float*)d_in[0];
    const int*   y    = (const int*)d_in[1];
    const int*   mask = (const int*)d_in[2];
    const float* tr   = (const float*)d_in[3];
    float* out = (float*)d_out;

    crf_scores<<<Bb, 512>>>(p, y, mask, tr);
    crf_forward<<<Bb / 2, 64>>>(p, mask, tr, out);
}